// round 10
// baseline (speedup 1.0000x reference)
#include <cuda_runtime.h>
#include <cuda_fp16.h>
#include <cstdint>

// ---------------------------------------------------------------------------
// LinearDecoder: mean_out = mean @ W^T + b ; logv = log((W*W) @ exp(logvar))
// B=131072, XDIM=128, YDIM=512. fp16 mma.sync (sm_80 PTX — legal on sm_103
// non-'a' ptxas target), f32 accumulate. Persistent CTAs, W resident in SMEM,
// cp.async double-buffered A tiles. Output: [mean_out][logv], f32.
// ---------------------------------------------------------------------------

#define DEVINL __device__ __forceinline__

static constexpr int BATCH    = 131072;
static constexpr int XD       = 128;            // K
static constexpr int YD       = 512;            // total N
static constexpr int MT       = 128;            // M tile
static constexpr int NT       = 256;            // N per CTA
static constexpr int M_TILES  = BATCH / MT;     // 1024
static constexpr int GX       = 37;             // 37*2*2 = 148 CTAs = 1 wave
static constexpr int NTHREADS = 256;            // 8 warps, 2(m) x 4(n) warp grid

// fp16 SMEM tiles padded to 136 halves/row (272 B): ldmatrix conflict-free.
static constexpr int AROW_H  = 136;
static constexpr int AROW_B  = AROW_H * 2;      // 272
static constexpr int SM_A0   = 0;                                // half[2][128][136]
static constexpr int SM_ABUF = MT * AROW_B;                      // 34816 per buffer
static constexpr int SM_B    = 2 * SM_ABUF;                      // 69632: half[256][136]
static constexpr int SM_ST   = SM_B + NT * AROW_B;               // 139264: f32 staging 64KB
static constexpr int SM_BIAS = SM_ST + MT * XD * 4;              // 204800
static constexpr int SM_TOTAL= SM_BIAS + NT * 4;                 // 205824 bytes

// ---------------- PTX helpers ----------------
DEVINL uint32_t smem_u32(const void* p) {
    uint32_t a;
    asm("{ .reg .u64 t; cvta.to.shared.u64 t, %1; cvt.u32.u64 %0, t; }" : "=r"(a) : "l"(p));
    return a;
}
DEVINL void ldm4(uint32_t* r, uint32_t addr) {
    asm volatile("ldmatrix.sync.aligned.m8n8.x4.shared.b16 {%0,%1,%2,%3}, [%4];"
                 : "=r"(r[0]), "=r"(r[1]), "=r"(r[2]), "=r"(r[3]) : "r"(addr));
}
DEVINL void mma_f16(float* c, const uint32_t* a, uint32_t b0, uint32_t b1) {
    asm volatile("mma.sync.aligned.m16n8k16.row.col.f32.f16.f16.f32 "
                 "{%0,%1,%2,%3}, {%4,%5,%6,%7}, {%8,%9}, {%0,%1,%2,%3};"
                 : "+f"(c[0]), "+f"(c[1]), "+f"(c[2]), "+f"(c[3])
                 : "r"(a[0]), "r"(a[1]), "r"(a[2]), "r"(a[3]), "r"(b0), "r"(b1));
}
DEVINL void cp_async16(uint32_t smem_dst, const void* gmem_src) {
    asm volatile("cp.async.cg.shared.global [%0], [%1], 16;"
                 :: "r"(smem_dst), "l"(gmem_src) : "memory");
}
#define CP_COMMIT()  asm volatile("cp.async.commit_group;" ::: "memory")
#define CP_WAIT0()   asm volatile("cp.async.wait_group 0;"  ::: "memory")

DEVINL uint32_t h2u(__half2 h) { return *reinterpret_cast<uint32_t*>(&h); }

// convert one float4 (optionally exp'd) to 4 halves and store as 8B to smem
DEVINL void cvt_store(char* smem, int byte_off, float4 v, int branch) {
    if (branch) { v.x = __expf(v.x); v.y = __expf(v.y); v.z = __expf(v.z); v.w = __expf(v.w); }
    uint2 u;
    u.x = h2u(__floats2half2_rn(v.x, v.y));
    u.y = h2u(__floats2half2_rn(v.z, v.w));
    *reinterpret_cast<uint2*>(smem + byte_off) = u;
}

// ---------------- kernel ----------------
__global__ void __launch_bounds__(NTHREADS, 1)
lindec_kernel(const float* __restrict__ mean, const float* __restrict__ logvar,
              const float* __restrict__ W, const float* __restrict__ bias,
              float* __restrict__ out) {
    extern __shared__ char smem[];
    const uint32_t sb  = smem_u32(smem);
    const int tid   = threadIdx.x;
    const int wid   = tid >> 5;
    const int lane  = tid & 31;
    const int branch = blockIdx.z;          // 0: mean, 1: variance
    const int nhalf  = blockIdx.y;
    const int n0g    = nhalf * NT;          // global N offset of this CTA

    const int wm = (wid >> 2) * 64;         // warp M origin within tile (0/64)
    const int wn = (wid & 3) * 64;          // warp N origin within NT (0..192)

    const float* Asrc = branch ? logvar : mean;
    float* outb = out + (size_t)branch * BATCH * YD + n0g;

    // ---- prologue: resident B = fp16(W[n0g:n0g+256,:]) (squared for branch 1) ----
    {
        const float* Wp = W + (size_t)n0g * XD;
#pragma unroll 4
        for (int idx = tid; idx < NT * (XD / 4); idx += NTHREADS) {
            const int r = idx >> 5, c4 = idx & 31;
            float4 v = *reinterpret_cast<const float4*>(Wp + (size_t)r * XD + c4 * 4);
            if (branch) { v.x *= v.x; v.y *= v.y; v.z *= v.z; v.w *= v.w; }
            uint2 u;
            u.x = h2u(__floats2half2_rn(v.x, v.y));
            u.y = h2u(__floats2half2_rn(v.z, v.w));
            *reinterpret_cast<uint2*>(smem + SM_B + r * AROW_B + c4 * 8) = u;
        }
        if (branch == 0)
            for (int n = tid; n < NT; n += NTHREADS)
                reinterpret_cast<float*>(smem + SM_BIAS)[n] = bias[n0g + n];
    }

    // ---- prologue: tile 0 A via cp.async -> staging -> convert ----
    {
        const float* src = Asrc + (size_t)blockIdx.x * MT * XD;
#pragma unroll
        for (int i = 0; i < 16; i++) {
            const int idx = tid + NTHREADS * i;
            cp_async16(sb + SM_ST + idx * 16, src + idx * 4);
        }
        CP_COMMIT(); CP_WAIT0();
#pragma unroll
        for (int i = 0; i < 16; i++) {
            const int idx = tid + NTHREADS * i;
            float4 v = reinterpret_cast<const float4*>(smem + SM_ST)[idx];
            const int r = idx >> 5, c4 = idx & 31;
            cvt_store(smem, SM_A0 + r * AROW_B + c4 * 8, v, branch);
        }
    }
    __syncthreads();

    // ldmatrix per-lane addressing
    const int a_r = lane & 15;              // A: row within m16 tile
    const int a_c = (lane >> 4) * 8;        // A: half offset (k0 or k0+8)
    const int b_r = (lane & 7) + ((lane >> 4) << 3);
    const int b_c = ((lane >> 3) & 1) * 8;

    uint32_t baddr[4];
#pragma unroll
    for (int nt = 0; nt < 4; nt++)
        baddr[nt] = sb + SM_B + (wn + nt * 16 + b_r) * AROW_B + (b_c) * 2;

    // bias pairs for this thread's output columns (branch 0)
    float2 bv[8];
    if (branch == 0) {
        const float* bsm = reinterpret_cast<const float*>(smem + SM_BIAS);
#pragma unroll
        for (int ni = 0; ni < 8; ni++)
            bv[ni] = *reinterpret_cast<const float2*>(bsm + wn + ni * 8 + 2 * (lane & 3));
    }

    int it = 0;
    for (int t = blockIdx.x; t < M_TILES; t += GX, ++it) {
        const int cur = it & 1;
        const bool has_next = (t + GX) < M_TILES;

        // kick off next tile's DRAM loads (hidden under this tile's MMA)
        if (has_next) {
            const float* src = Asrc + (size_t)(t + GX) * MT * XD;
#pragma unroll
            for (int i = 0; i < 16; i++) {
                const int idx = tid + NTHREADS * i;
                cp_async16(sb + SM_ST + idx * 16, src + idx * 4);
            }
            CP_COMMIT();
        }

        // ---- MMA: 64x64 per warp, K=128 in 8 k16 steps ----
        float acc[4][8][4];
#pragma unroll
        for (int mi = 0; mi < 4; mi++)
#pragma unroll
            for (int ni = 0; ni < 8; ni++)
#pragma unroll
                for (int q = 0; q < 4; q++) acc[mi][ni][q] = 0.f;

        uint32_t aaddr[4];
#pragma unroll
        for (int mi = 0; mi < 4; mi++)
            aaddr[mi] = sb + SM_A0 + cur * SM_ABUF + (wm + mi * 16 + a_r) * AROW_B + a_c * 2;

#pragma unroll
        for (int k = 0; k < 8; k++) {
            uint32_t af[4][4], bf[4][4];
#pragma unroll
            for (int mi = 0; mi < 4; mi++) ldm4(af[mi], aaddr[mi] + k * 32);
#pragma unroll
            for (int nt = 0; nt < 4; nt++) ldm4(bf[nt], baddr[nt] + k * 32);
#pragma unroll
            for (int mi = 0; mi < 4; mi++)
#pragma unroll
                for (int ni = 0; ni < 8; ni++)
                    mma_f16(acc[mi][ni], af[mi], bf[ni >> 1][(ni & 1) * 2], bf[ni >> 1][(ni & 1) * 2 + 1]);
        }

        // ---- epilogue: transform + store ----
        {
            const size_t rbase = (size_t)t * MT + wm + (lane >> 2);
#pragma unroll
            for (int mi = 0; mi < 4; mi++) {
                float* p0 = outb + (rbase + mi * 16) * YD;
                float* p1 = p0 + 8 * YD;
#pragma unroll
                for (int ni = 0; ni < 8; ni++) {
                    const int c = wn + ni * 8 + 2 * (lane & 3);
                    float2 v0, v1;
                    if (branch == 0) {
                        v0.x = acc[mi][ni][0] + bv[ni].x;  v0.y = acc[mi][ni][1] + bv[ni].y;
                        v1.x = acc[mi][ni][2] + bv[ni].x;  v1.y = acc[mi][ni][3] + bv[ni].y;
                    } else {
                        v0.x = __logf(acc[mi][ni][0]);  v0.y = __logf(acc[mi][ni][1]);
                        v1.x = __logf(acc[mi][ni][2]);  v1.y = __logf(acc[mi][ni][3]);
                    }
                    *reinterpret_cast<float2*>(p0 + c) = v0;
                    *reinterpret_cast<float2*>(p1 + c) = v1;
                }
            }
        }

        // ---- drain cp.async, convert into the other A buffer ----
        if (has_next) {
            CP_WAIT0();
            const int nxt = cur ^ 1;
#pragma unroll
            for (int i = 0; i < 16; i++) {
                const int idx = tid + NTHREADS * i;
                float4 v = reinterpret_cast<const float4*>(smem + SM_ST)[idx];
                const int r = idx >> 5, c4 = idx & 31;
                cvt_store(smem, SM_A0 + nxt * SM_ABUF + r * AROW_B + c4 * 8, v, branch);
            }
        }
        __syncthreads();
    }
}

// ---------------- launch ----------------
extern "C" void kernel_launch(void* const* d_in, const int* in_sizes, int n_in,
                              void* d_out, int out_size) {
    const float* mean   = (const float*)d_in[0];
    const float* logvar = (const float*)d_in[1];
    const float* W      = (const float*)d_in[2];
    const float* bias   = (const float*)d_in[3];
    float* out = (float*)d_out;

    cudaFuncSetAttribute(lindec_kernel, cudaFuncAttributeMaxDynamicSharedMemorySize, SM_TOTAL);

    dim3 grid(GX, 2, 2);   // x: M-tile stride groups, y: N half, z: branch
    lindec_kernel<<<grid, NTHREADS, SM_TOTAL>>>(mean, logvar, W, bias, out);
}

// round 11
// speedup vs baseline: 1.0030x; 1.0030x over previous
#include <cuda_runtime.h>
#include <cuda_fp16.h>
#include <cstdint>

// ---------------------------------------------------------------------------
// LinearDecoder: mean_out = mean @ W^T + b ; logv = log((W*W) @ exp(logvar))
// B=131072, XDIM=128, YDIM=512. fp16 mma.sync (sm_80 PTX — legal on sm_103
// non-'a' ptxas target), f32 accumulate. Persistent CTAs, W resident in SMEM,
// cp.async double-buffered A tiles. Output: [mean_out][logv], f32.
// ---------------------------------------------------------------------------

#define DEVINL __device__ __forceinline__

static constexpr int BATCH    = 131072;
static constexpr int XD       = 128;            // K
static constexpr int YD       = 512;            // total N
static constexpr int MT       = 128;            // M tile
static constexpr int NT       = 256;            // N per CTA
static constexpr int M_TILES  = BATCH / MT;     // 1024
static constexpr int GX       = 37;             // 37*2*2 = 148 CTAs = 1 wave
static constexpr int NTHREADS = 256;            // 8 warps, 2(m) x 4(n) warp grid

// fp16 SMEM tiles padded to 136 halves/row (272 B): ldmatrix conflict-free.
static constexpr int AROW_H  = 136;
static constexpr int AROW_B  = AROW_H * 2;      // 272
static constexpr int SM_A0   = 0;                                // half[2][128][136]
static constexpr int SM_ABUF = MT * AROW_B;                      // 34816 per buffer
static constexpr int SM_B    = 2 * SM_ABUF;                      // 69632: half[256][136]
static constexpr int SM_ST   = SM_B + NT * AROW_B;               // 139264: f32 staging 64KB
static constexpr int SM_BIAS = SM_ST + MT * XD * 4;              // 204800
static constexpr int SM_TOTAL= SM_BIAS + NT * 4;                 // 205824 bytes

// ---------------- PTX helpers ----------------
DEVINL uint32_t smem_u32(const void* p) {
    uint32_t a;
    asm("{ .reg .u64 t; cvta.to.shared.u64 t, %1; cvt.u32.u64 %0, t; }" : "=r"(a) : "l"(p));
    return a;
}
DEVINL void ldm4(uint32_t* r, uint32_t addr) {
    asm volatile("ldmatrix.sync.aligned.m8n8.x4.shared.b16 {%0,%1,%2,%3}, [%4];"
                 : "=r"(r[0]), "=r"(r[1]), "=r"(r[2]), "=r"(r[3]) : "r"(addr));
}
DEVINL void mma_f16(float* c, const uint32_t* a, uint32_t b0, uint32_t b1) {
    asm volatile("mma.sync.aligned.m16n8k16.row.col.f32.f16.f16.f32 "
                 "{%0,%1,%2,%3}, {%4,%5,%6,%7}, {%8,%9}, {%0,%1,%2,%3};"
                 : "+f"(c[0]), "+f"(c[1]), "+f"(c[2]), "+f"(c[3])
                 : "r"(a[0]), "r"(a[1]), "r"(a[2]), "r"(a[3]), "r"(b0), "r"(b1));
}
DEVINL void cp_async16(uint32_t smem_dst, const void* gmem_src) {
    asm volatile("cp.async.cg.shared.global [%0], [%1], 16;"
                 :: "r"(smem_dst), "l"(gmem_src) : "memory");
}
#define CP_COMMIT()  asm volatile("cp.async.commit_group;" ::: "memory")
#define CP_WAIT0()   asm volatile("cp.async.wait_group 0;"  ::: "memory")

DEVINL uint32_t h2u(__half2 h) { return *reinterpret_cast<uint32_t*>(&h); }

// convert one float4 (optionally exp'd) to 4 halves and store as 8B to smem
DEVINL void cvt_store(char* smem, int byte_off, float4 v, int branch) {
    if (branch) { v.x = __expf(v.x); v.y = __expf(v.y); v.z = __expf(v.z); v.w = __expf(v.w); }
    uint2 u;
    u.x = h2u(__floats2half2_rn(v.x, v.y));
    u.y = h2u(__floats2half2_rn(v.z, v.w));
    *reinterpret_cast<uint2*>(smem + byte_off) = u;
}

// ---------------- kernel ----------------
__global__ void __launch_bounds__(NTHREADS, 1)
lindec_kernel(const float* __restrict__ mean, const float* __restrict__ logvar,
              const float* __restrict__ W, const float* __restrict__ bias,
              float* __restrict__ out) {
    extern __shared__ char smem[];
    const uint32_t sb  = smem_u32(smem);
    const int tid   = threadIdx.x;
    const int wid   = tid >> 5;
    const int lane  = tid & 31;
    const int branch = blockIdx.z;          // 0: mean, 1: variance
    const int nhalf  = blockIdx.y;
    const int n0g    = nhalf * NT;          // global N offset of this CTA

    const int wm = (wid >> 2) * 64;         // warp M origin within tile (0/64)
    const int wn = (wid & 3) * 64;          // warp N origin within NT (0..192)

    const float* Asrc = branch ? logvar : mean;
    float* outb = out + (size_t)branch * BATCH * YD + n0g;

    // ---- prologue: resident B = fp16(W[n0g:n0g+256,:]) (squared for branch 1) ----
    {
        const float* Wp = W + (size_t)n0g * XD;
#pragma unroll 4
        for (int idx = tid; idx < NT * (XD / 4); idx += NTHREADS) {
            const int r = idx >> 5, c4 = idx & 31;
            float4 v = *reinterpret_cast<const float4*>(Wp + (size_t)r * XD + c4 * 4);
            if (branch) { v.x *= v.x; v.y *= v.y; v.z *= v.z; v.w *= v.w; }
            uint2 u;
            u.x = h2u(__floats2half2_rn(v.x, v.y));
            u.y = h2u(__floats2half2_rn(v.z, v.w));
            *reinterpret_cast<uint2*>(smem + SM_B + r * AROW_B + c4 * 8) = u;
        }
        if (branch == 0)
            for (int n = tid; n < NT; n += NTHREADS)
                reinterpret_cast<float*>(smem + SM_BIAS)[n] = bias[n0g + n];
    }

    // ---- prologue: tile 0 A via cp.async -> staging -> convert ----
    {
        const float* src = Asrc + (size_t)blockIdx.x * MT * XD;
#pragma unroll
        for (int i = 0; i < 16; i++) {
            const int idx = tid + NTHREADS * i;
            cp_async16(sb + SM_ST + idx * 16, src + idx * 4);
        }
        CP_COMMIT(); CP_WAIT0();
#pragma unroll
        for (int i = 0; i < 16; i++) {
            const int idx = tid + NTHREADS * i;
            float4 v = reinterpret_cast<const float4*>(smem + SM_ST)[idx];
            const int r = idx >> 5, c4 = idx & 31;
            cvt_store(smem, SM_A0 + r * AROW_B + c4 * 8, v, branch);
        }
    }
    __syncthreads();

    // ldmatrix per-lane addressing
    const int a_r = lane & 15;              // A: row within m16 tile
    const int a_c = (lane >> 4) * 8;        // A: half offset (k0 or k0+8)
    const int b_r = (lane & 7) + ((lane >> 4) << 3);
    const int b_c = ((lane >> 3) & 1) * 8;

    uint32_t baddr[4];
#pragma unroll
    for (int nt = 0; nt < 4; nt++)
        baddr[nt] = sb + SM_B + (wn + nt * 16 + b_r) * AROW_B + (b_c) * 2;

    // bias pairs for this thread's output columns (branch 0)
    float2 bv[8];
    if (branch == 0) {
        const float* bsm = reinterpret_cast<const float*>(smem + SM_BIAS);
#pragma unroll
        for (int ni = 0; ni < 8; ni++)
            bv[ni] = *reinterpret_cast<const float2*>(bsm + wn + ni * 8 + 2 * (lane & 3));
    }

    int it = 0;
    for (int t = blockIdx.x; t < M_TILES; t += GX, ++it) {
        const int cur = it & 1;
        const bool has_next = (t + GX) < M_TILES;

        // kick off next tile's DRAM loads (hidden under this tile's MMA)
        if (has_next) {
            const float* src = Asrc + (size_t)(t + GX) * MT * XD;
#pragma unroll
            for (int i = 0; i < 16; i++) {
                const int idx = tid + NTHREADS * i;
                cp_async16(sb + SM_ST + idx * 16, src + idx * 4);
            }
            CP_COMMIT();
        }

        // ---- MMA: 64x64 per warp, K=128 in 8 k16 steps ----
        float acc[4][8][4];
#pragma unroll
        for (int mi = 0; mi < 4; mi++)
#pragma unroll
            for (int ni = 0; ni < 8; ni++)
#pragma unroll
                for (int q = 0; q < 4; q++) acc[mi][ni][q] = 0.f;

        uint32_t aaddr[4];
#pragma unroll
        for (int mi = 0; mi < 4; mi++)
            aaddr[mi] = sb + SM_A0 + cur * SM_ABUF + (wm + mi * 16 + a_r) * AROW_B + a_c * 2;

#pragma unroll
        for (int k = 0; k < 8; k++) {
            uint32_t af[4][4], bf[4][4];
#pragma unroll
            for (int mi = 0; mi < 4; mi++) ldm4(af[mi], aaddr[mi] + k * 32);
#pragma unroll
            for (int nt = 0; nt < 4; nt++) ldm4(bf[nt], baddr[nt] + k * 32);
#pragma unroll
            for (int mi = 0; mi < 4; mi++)
#pragma unroll
                for (int ni = 0; ni < 8; ni++)
                    mma_f16(acc[mi][ni], af[mi], bf[ni >> 1][(ni & 1) * 2], bf[ni >> 1][(ni & 1) * 2 + 1]);
        }

        // ---- epilogue: transform + store ----
        {
            const size_t rbase = (size_t)t * MT + wm + (lane >> 2);
#pragma unroll
            for (int mi = 0; mi < 4; mi++) {
                float* p0 = outb + (rbase + mi * 16) * YD;
                float* p1 = p0 + 8 * YD;
#pragma unroll
                for (int ni = 0; ni < 8; ni++) {
                    const int c = wn + ni * 8 + 2 * (lane & 3);
                    float2 v0, v1;
                    if (branch == 0) {
                        v0.x = acc[mi][ni][0] + bv[ni].x;  v0.y = acc[mi][ni][1] + bv[ni].y;
                        v1.x = acc[mi][ni][2] + bv[ni].x;  v1.y = acc[mi][ni][3] + bv[ni].y;
                    } else {
                        v0.x = __logf(acc[mi][ni][0]);  v0.y = __logf(acc[mi][ni][1]);
                        v1.x = __logf(acc[mi][ni][2]);  v1.y = __logf(acc[mi][ni][3]);
                    }
                    *reinterpret_cast<float2*>(p0 + c) = v0;
                    *reinterpret_cast<float2*>(p1 + c) = v1;
                }
            }
        }

        // ---- drain cp.async, convert into the other A buffer ----
        if (has_next) {
            CP_WAIT0();
            const int nxt = cur ^ 1;
#pragma unroll
            for (int i = 0; i < 16; i++) {
                const int idx = tid + NTHREADS * i;
                float4 v = reinterpret_cast<const float4*>(smem + SM_ST)[idx];
                const int r = idx >> 5, c4 = idx & 31;
                cvt_store(smem, SM_A0 + nxt * SM_ABUF + r * AROW_B + c4 * 8, v, branch);
            }
        }
        __syncthreads();
    }
}

// ---------------- launch ----------------
extern "C" void kernel_launch(void* const* d_in, const int* in_sizes, int n_in,
                              void* d_out, int out_size) {
    const float* mean   = (const float*)d_in[0];
    const float* logvar = (const float*)d_in[1];
    const float* W      = (const float*)d_in[2];
    const float* bias   = (const float*)d_in[3];
    float* out = (float*)d_out;

    cudaFuncSetAttribute(lindec_kernel, cudaFuncAttributeMaxDynamicSharedMemorySize, SM_TOTAL);

    dim3 grid(GX, 2, 2);   // x: M-tile stride groups, y: N half, z: branch
    lindec_kernel<<<grid, NTHREADS, SM_TOTAL>>>(mean, logvar, W, bias, out);
}

// round 12
// speedup vs baseline: 1.0032x; 1.0002x over previous
#include <cuda_runtime.h>
#include <cuda_fp16.h>
#include <cstdint>

// ---------------------------------------------------------------------------
// LinearDecoder: mean_out = mean @ W^T + b ; logv = log((W*W) @ exp(logvar))
// B=131072, XDIM=128, YDIM=512. fp16 mma.sync (sm_80 PTX — legal on sm_103
// non-'a' ptxas target), f32 accumulate. Persistent CTAs, W resident in SMEM,
// cp.async double-buffered A tiles. Output: [mean_out][logv], f32.
// ---------------------------------------------------------------------------

#define DEVINL __device__ __forceinline__

static constexpr int BATCH    = 131072;
static constexpr int XD       = 128;            // K
static constexpr int YD       = 512;            // total N
static constexpr int MT       = 128;            // M tile
static constexpr int NT       = 256;            // N per CTA
static constexpr int M_TILES  = BATCH / MT;     // 1024
static constexpr int GX       = 37;             // 37*2*2 = 148 CTAs = 1 wave
static constexpr int NTHREADS = 256;            // 8 warps, 2(m) x 4(n) warp grid

// fp16 SMEM tiles padded to 136 halves/row (272 B): ldmatrix conflict-free.
static constexpr int AROW_H  = 136;
static constexpr int AROW_B  = AROW_H * 2;      // 272
static constexpr int SM_A0   = 0;                                // half[2][128][136]
static constexpr int SM_ABUF = MT * AROW_B;                      // 34816 per buffer
static constexpr int SM_B    = 2 * SM_ABUF;                      // 69632: half[256][136]
static constexpr int SM_ST   = SM_B + NT * AROW_B;               // 139264: f32 staging 64KB
static constexpr int SM_BIAS = SM_ST + MT * XD * 4;              // 204800
static constexpr int SM_TOTAL= SM_BIAS + NT * 4;                 // 205824 bytes

// ---------------- PTX helpers ----------------
DEVINL uint32_t smem_u32(const void* p) {
    uint32_t a;
    asm("{ .reg .u64 t; cvta.to.shared.u64 t, %1; cvt.u32.u64 %0, t; }" : "=r"(a) : "l"(p));
    return a;
}
DEVINL void ldm4(uint32_t* r, uint32_t addr) {
    asm volatile("ldmatrix.sync.aligned.m8n8.x4.shared.b16 {%0,%1,%2,%3}, [%4];"
                 : "=r"(r[0]), "=r"(r[1]), "=r"(r[2]), "=r"(r[3]) : "r"(addr));
}
DEVINL void mma_f16(float* c, const uint32_t* a, uint32_t b0, uint32_t b1) {
    asm volatile("mma.sync.aligned.m16n8k16.row.col.f32.f16.f16.f32 "
                 "{%0,%1,%2,%3}, {%4,%5,%6,%7}, {%8,%9}, {%0,%1,%2,%3};"
                 : "+f"(c[0]), "+f"(c[1]), "+f"(c[2]), "+f"(c[3])
                 : "r"(a[0]), "r"(a[1]), "r"(a[2]), "r"(a[3]), "r"(b0), "r"(b1));
}
DEVINL void cp_async16(uint32_t smem_dst, const void* gmem_src) {
    asm volatile("cp.async.cg.shared.global [%0], [%1], 16;"
                 :: "r"(smem_dst), "l"(gmem_src) : "memory");
}
#define CP_COMMIT()  asm volatile("cp.async.commit_group;" ::: "memory")
#define CP_WAIT0()   asm volatile("cp.async.wait_group 0;"  ::: "memory")

DEVINL uint32_t h2u(__half2 h) { return *reinterpret_cast<uint32_t*>(&h); }

// convert one float4 (optionally exp'd) to 4 halves and store as 8B to smem
DEVINL void cvt_store(char* smem, int byte_off, float4 v, int branch) {
    if (branch) { v.x = __expf(v.x); v.y = __expf(v.y); v.z = __expf(v.z); v.w = __expf(v.w); }
    uint2 u;
    u.x = h2u(__floats2half2_rn(v.x, v.y));
    u.y = h2u(__floats2half2_rn(v.z, v.w));
    *reinterpret_cast<uint2*>(smem + byte_off) = u;
}

// ---------------- kernel ----------------
__global__ void __launch_bounds__(NTHREADS, 1)
lindec_kernel(const float* __restrict__ mean, const float* __restrict__ logvar,
              const float* __restrict__ W, const float* __restrict__ bias,
              float* __restrict__ out) {
    extern __shared__ char smem[];
    const uint32_t sb  = smem_u32(smem);
    const int tid   = threadIdx.x;
    const int wid   = tid >> 5;
    const int lane  = tid & 31;
    const int branch = blockIdx.z;          // 0: mean, 1: variance
    const int nhalf  = blockIdx.y;
    const int n0g    = nhalf * NT;          // global N offset of this CTA

    const int wm = (wid >> 2) * 64;         // warp M origin within tile (0/64)
    const int wn = (wid & 3) * 64;          // warp N origin within NT (0..192)

    const float* Asrc = branch ? logvar : mean;
    float* outb = out + (size_t)branch * BATCH * YD + n0g;

    // ---- prologue: resident B = fp16(W[n0g:n0g+256,:]) (squared for branch 1) ----
    {
        const float* Wp = W + (size_t)n0g * XD;
#pragma unroll 4
        for (int idx = tid; idx < NT * (XD / 4); idx += NTHREADS) {
            const int r = idx >> 5, c4 = idx & 31;
            float4 v = *reinterpret_cast<const float4*>(Wp + (size_t)r * XD + c4 * 4);
            if (branch) { v.x *= v.x; v.y *= v.y; v.z *= v.z; v.w *= v.w; }
            uint2 u;
            u.x = h2u(__floats2half2_rn(v.x, v.y));
            u.y = h2u(__floats2half2_rn(v.z, v.w));
            *reinterpret_cast<uint2*>(smem + SM_B + r * AROW_B + c4 * 8) = u;
        }
        if (branch == 0)
            for (int n = tid; n < NT; n += NTHREADS)
                reinterpret_cast<float*>(smem + SM_BIAS)[n] = bias[n0g + n];
    }

    // ---- prologue: tile 0 A via cp.async -> staging -> convert ----
    {
        const float* src = Asrc + (size_t)blockIdx.x * MT * XD;
#pragma unroll
        for (int i = 0; i < 16; i++) {
            const int idx = tid + NTHREADS * i;
            cp_async16(sb + SM_ST + idx * 16, src + idx * 4);
        }
        CP_COMMIT(); CP_WAIT0();
#pragma unroll
        for (int i = 0; i < 16; i++) {
            const int idx = tid + NTHREADS * i;
            float4 v = reinterpret_cast<const float4*>(smem + SM_ST)[idx];
            const int r = idx >> 5, c4 = idx & 31;
            cvt_store(smem, SM_A0 + r * AROW_B + c4 * 8, v, branch);
        }
    }
    __syncthreads();

    // ldmatrix per-lane addressing
    const int a_r = lane & 15;              // A: row within m16 tile
    const int a_c = (lane >> 4) * 8;        // A: half offset (k0 or k0+8)
    const int b_r = (lane & 7) + ((lane >> 4) << 3);
    const int b_c = ((lane >> 3) & 1) * 8;

    uint32_t baddr[4];
#pragma unroll
    for (int nt = 0; nt < 4; nt++)
        baddr[nt] = sb + SM_B + (wn + nt * 16 + b_r) * AROW_B + (b_c) * 2;

    // bias pairs for this thread's output columns (branch 0)
    float2 bv[8];
    if (branch == 0) {
        const float* bsm = reinterpret_cast<const float*>(smem + SM_BIAS);
#pragma unroll
        for (int ni = 0; ni < 8; ni++)
            bv[ni] = *reinterpret_cast<const float2*>(bsm + wn + ni * 8 + 2 * (lane & 3));
    }

    int it = 0;
    for (int t = blockIdx.x; t < M_TILES; t += GX, ++it) {
        const int cur = it & 1;
        const bool has_next = (t + GX) < M_TILES;

        // kick off next tile's DRAM loads (hidden under this tile's MMA)
        if (has_next) {
            const float* src = Asrc + (size_t)(t + GX) * MT * XD;
#pragma unroll
            for (int i = 0; i < 16; i++) {
                const int idx = tid + NTHREADS * i;
                cp_async16(sb + SM_ST + idx * 16, src + idx * 4);
            }
            CP_COMMIT();
        }

        // ---- MMA: 64x64 per warp, K=128 in 8 k16 steps ----
        float acc[4][8][4];
#pragma unroll
        for (int mi = 0; mi < 4; mi++)
#pragma unroll
            for (int ni = 0; ni < 8; ni++)
#pragma unroll
                for (int q = 0; q < 4; q++) acc[mi][ni][q] = 0.f;

        uint32_t aaddr[4];
#pragma unroll
        for (int mi = 0; mi < 4; mi++)
            aaddr[mi] = sb + SM_A0 + cur * SM_ABUF + (wm + mi * 16 + a_r) * AROW_B + a_c * 2;

#pragma unroll
        for (int k = 0; k < 8; k++) {
            uint32_t af[4][4], bf[4][4];
#pragma unroll
            for (int mi = 0; mi < 4; mi++) ldm4(af[mi], aaddr[mi] + k * 32);
#pragma unroll
            for (int nt = 0; nt < 4; nt++) ldm4(bf[nt], baddr[nt] + k * 32);
#pragma unroll
            for (int mi = 0; mi < 4; mi++)
#pragma unroll
                for (int ni = 0; ni < 8; ni++)
                    mma_f16(acc[mi][ni], af[mi], bf[ni >> 1][(ni & 1) * 2], bf[ni >> 1][(ni & 1) * 2 + 1]);
        }

        // ---- epilogue: transform + store ----
        {
            const size_t rbase = (size_t)t * MT + wm + (lane >> 2);
#pragma unroll
            for (int mi = 0; mi < 4; mi++) {
                float* p0 = outb + (rbase + mi * 16) * YD;
                float* p1 = p0 + 8 * YD;
#pragma unroll
                for (int ni = 0; ni < 8; ni++) {
                    const int c = wn + ni * 8 + 2 * (lane & 3);
                    float2 v0, v1;
                    if (branch == 0) {
                        v0.x = acc[mi][ni][0] + bv[ni].x;  v0.y = acc[mi][ni][1] + bv[ni].y;
                        v1.x = acc[mi][ni][2] + bv[ni].x;  v1.y = acc[mi][ni][3] + bv[ni].y;
                    } else {
                        v0.x = __logf(acc[mi][ni][0]);  v0.y = __logf(acc[mi][ni][1]);
                        v1.x = __logf(acc[mi][ni][2]);  v1.y = __logf(acc[mi][ni][3]);
                    }
                    *reinterpret_cast<float2*>(p0 + c) = v0;
                    *reinterpret_cast<float2*>(p1 + c) = v1;
                }
            }
        }

        // ---- drain cp.async, convert into the other A buffer ----
        if (has_next) {
            CP_WAIT0();
            const int nxt = cur ^ 1;
#pragma unroll
            for (int i = 0; i < 16; i++) {
                const int idx = tid + NTHREADS * i;
                float4 v = reinterpret_cast<const float4*>(smem + SM_ST)[idx];
                const int r = idx >> 5, c4 = idx & 31;
                cvt_store(smem, SM_A0 + nxt * SM_ABUF + r * AROW_B + c4 * 8, v, branch);
            }
        }
        __syncthreads();
    }
}

// ---------------- launch ----------------
extern "C" void kernel_launch(void* const* d_in, const int* in_sizes, int n_in,
                              void* d_out, int out_size) {
    const float* mean   = (const float*)d_in[0];
    const float* logvar = (const float*)d_in[1];
    const float* W      = (const float*)d_in[2];
    const float* bias   = (const float*)d_in[3];
    float* out = (float*)d_out;

    cudaFuncSetAttribute(lindec_kernel, cudaFuncAttributeMaxDynamicSharedMemorySize, SM_TOTAL);

    dim3 grid(GX, 2, 2);   // x: M-tile stride groups, y: N half, z: branch
    lindec_kernel<<<grid, NTHREADS, SM_TOTAL>>>(mean, logvar, W, bias, out);
}

// round 13
// speedup vs baseline: 1.0535x; 1.0502x over previous
#include <cuda_runtime.h>
#include <cuda_fp16.h>
#include <cstdint>

// ---------------------------------------------------------------------------
// LinearDecoder: mean_out = mean @ W^T + b ; logv = log((W*W) @ exp(logvar))
// B=131072, XDIM=128, YDIM=512. fp16 mma.sync, f32 accumulate.
// 512 threads/CTA, two phase-decoupled 8-warp groups (named barriers), each
// owning a 64-row M-half with private cp.async staging + double-buffered fp16
// A. Shared resident W slice in SMEM. Output: [mean_out][logv], f32.
// ---------------------------------------------------------------------------

#define DEVINL __device__ __forceinline__

static constexpr int BATCH    = 131072;
static constexpr int XD       = 128;            // K
static constexpr int YD       = 512;            // total N
static constexpr int MT       = 128;            // M tile (two 64-row groups)
static constexpr int GM       = 64;             // rows per group
static constexpr int NT       = 256;            // N per CTA
static constexpr int M_TILES  = BATCH / MT;     // 1024
static constexpr int GX       = 37;             // 37*2*2 = 148 CTAs = 1 wave
static constexpr int NTHREADS = 512;            // 16 warps: 2 groups x (2m x 4n)

// fp16 rows padded to 136 halves (272 B): ldmatrix conflict-free.
static constexpr int ROW_H   = 136;
static constexpr int ROW_B   = ROW_H * 2;       // 272
static constexpr int SM_B    = 0;                               // half[256][136]
static constexpr int SM_BIAS = SM_B + NT * ROW_B;               // 69632 (+1024)
static constexpr int SM_A    = SM_BIAS + 1024;                  // 70656: half[2g][2buf][64][136]
static constexpr int A_BUF   = GM * ROW_B;                      // 17408
static constexpr int SM_ST   = SM_A + 4 * A_BUF;                // 140288: f32[2g][64][128]
static constexpr int ST_BUF  = GM * XD * 4;                     // 32768
static constexpr int SM_TOTAL= SM_ST + 2 * ST_BUF;              // 205824 bytes

// ---------------- PTX helpers ----------------
DEVINL uint32_t smem_u32(const void* p) {
    uint32_t a;
    asm("{ .reg .u64 t; cvta.to.shared.u64 t, %1; cvt.u32.u64 %0, t; }" : "=r"(a) : "l"(p));
    return a;
}
DEVINL void ldm4(uint32_t* r, uint32_t addr) {
    asm volatile("ldmatrix.sync.aligned.m8n8.x4.shared.b16 {%0,%1,%2,%3}, [%4];"
                 : "=r"(r[0]), "=r"(r[1]), "=r"(r[2]), "=r"(r[3]) : "r"(addr));
}
DEVINL void mma_f16(float* c, const uint32_t* a, uint32_t b0, uint32_t b1) {
    asm volatile("mma.sync.aligned.m16n8k16.row.col.f32.f16.f16.f32 "
                 "{%0,%1,%2,%3}, {%4,%5,%6,%7}, {%8,%9}, {%0,%1,%2,%3};"
                 : "+f"(c[0]), "+f"(c[1]), "+f"(c[2]), "+f"(c[3])
                 : "r"(a[0]), "r"(a[1]), "r"(a[2]), "r"(a[3]), "r"(b0), "r"(b1));
}
DEVINL void cp_async16(uint32_t smem_dst, const void* gmem_src) {
    asm volatile("cp.async.cg.shared.global [%0], [%1], 16;"
                 :: "r"(smem_dst), "l"(gmem_src) : "memory");
}
#define CP_COMMIT()  asm volatile("cp.async.commit_group;" ::: "memory")
#define CP_WAIT0()   asm volatile("cp.async.wait_group 0;"  ::: "memory")
#define GBAR(id)     asm volatile("bar.sync %0, %1;" :: "r"(id), "r"(256) : "memory")

DEVINL uint32_t h2u(__half2 h) { return *reinterpret_cast<uint32_t*>(&h); }

// convert one float4 (optionally exp'd) to 4 halves, store 8B to smem
DEVINL void cvt_store(char* smem_c, int byte_off, float4 v, int branch) {
    if (branch) { v.x = __expf(v.x); v.y = __expf(v.y); v.z = __expf(v.z); v.w = __expf(v.w); }
    uint2 u;
    u.x = h2u(__floats2half2_rn(v.x, v.y));
    u.y = h2u(__floats2half2_rn(v.z, v.w));
    *reinterpret_cast<uint2*>(smem_c + byte_off) = u;
}

// ---------------- kernel ----------------
__global__ void __launch_bounds__(NTHREADS, 1)
lindec_kernel(const float* __restrict__ mean, const float* __restrict__ logvar,
              const float* __restrict__ W, const float* __restrict__ bias,
              float* __restrict__ out) {
    extern __shared__ char smem[];
    const uint32_t sb = smem_u32(smem);
    const int tid  = threadIdx.x;
    const int wid  = tid >> 5;
    const int lane = tid & 31;
    const int branch = blockIdx.z;          // 0: mean, 1: variance
    const int n0g    = blockIdx.y * NT;     // global N offset

    const int g    = wid >> 3;              // group 0/1 -> M rows [64g, 64g+64)
    const int gtid = tid & 255;             // thread id within group
    const int gw   = wid & 7;               // warp id within group
    const int wm   = (gw >> 2) * 32;        // warp M origin within group
    const int wn   = (gw & 3) * 64;         // warp N origin

    const float* Asrc = branch ? logvar : mean;
    float* outb = out + (size_t)branch * BATCH * YD + n0g;

    const uint32_t stg = sb + SM_ST + g * ST_BUF;           // this group's staging
    char* stg_c        = smem + SM_ST + g * ST_BUF;
    char* abuf_c       = smem + SM_A + g * 2 * A_BUF;       // 2 fp16 buffers

    // ---- prologue: resident B = fp16(W[n0g:+256,:]) (squared for branch 1) ----
    {
        const float* Wp = W + (size_t)n0g * XD;
#pragma unroll 4
        for (int idx = tid; idx < NT * (XD / 4); idx += NTHREADS) {
            const int r = idx >> 5, c4 = idx & 31;
            float4 v = *reinterpret_cast<const float4*>(Wp + (size_t)r * XD + c4 * 4);
            if (branch) { v.x *= v.x; v.y *= v.y; v.z *= v.z; v.w *= v.w; }
            uint2 u;
            u.x = h2u(__floats2half2_rn(v.x, v.y));
            u.y = h2u(__floats2half2_rn(v.z, v.w));
            *reinterpret_cast<uint2*>(smem + SM_B + r * ROW_B + c4 * 8) = u;
        }
        if (branch == 0)
            for (int n = tid; n < NT; n += NTHREADS)
                reinterpret_cast<float*>(smem + SM_BIAS)[n] = bias[n0g + n];
    }

    // ---- prologue: tile 0 A half for this group ----
    {
        const float* src = Asrc + ((size_t)blockIdx.x * MT + g * GM) * XD;
#pragma unroll
        for (int i = 0; i < 8; i++) {
            const int idx = gtid + 256 * i;
            cp_async16(stg + idx * 16, src + idx * 4);
        }
        CP_COMMIT(); CP_WAIT0();
#pragma unroll
        for (int i = 0; i < 8; i++) {
            const int idx = gtid + 256 * i;
            float4 v = reinterpret_cast<const float4*>(stg_c)[idx];
            const int r = idx >> 5, c4 = idx & 31;
            cvt_store(abuf_c, r * ROW_B + c4 * 8, v, branch);
        }
    }
    __syncthreads();   // B + both groups' tile-0 A ready

    // ldmatrix per-lane addressing
    const int a_r = lane & 15;
    const int a_c = (lane >> 4) * 8;
    const int b_r = (lane & 7) + ((lane >> 4) << 3);
    const int b_c = ((lane >> 3) & 1) * 8;

    uint32_t baddr[4];
#pragma unroll
    for (int nt = 0; nt < 4; nt++)
        baddr[nt] = sb + SM_B + (wn + nt * 16 + b_r) * ROW_B + b_c * 2;

    const float* bsm = reinterpret_cast<const float*>(smem + SM_BIAS);

    int it = 0;
    for (int t = blockIdx.x; t < M_TILES; t += GX, ++it) {
        const int cur = it & 1;
        const bool has_next = (t + GX) < M_TILES;

        // kick off next tile's DRAM loads (hidden under this tile's MMA)
        if (has_next) {
            const float* src = Asrc + ((size_t)(t + GX) * MT + g * GM) * XD;
#pragma unroll
            for (int i = 0; i < 8; i++) {
                const int idx = gtid + 256 * i;
                cp_async16(stg + idx * 16, src + idx * 4);
            }
            CP_COMMIT();
        }

        // ---- MMA: 32x64 per warp, K=128 in 8 k16 steps ----
        float acc[2][8][4];
#pragma unroll
        for (int mi = 0; mi < 2; mi++)
#pragma unroll
            for (int ni = 0; ni < 8; ni++)
#pragma unroll
                for (int q = 0; q < 4; q++) acc[mi][ni][q] = 0.f;

        uint32_t aaddr[2];
#pragma unroll
        for (int mi = 0; mi < 2; mi++)
            aaddr[mi] = sb + SM_A + (g * 2 + cur) * A_BUF
                      + (wm + mi * 16 + a_r) * ROW_B + a_c * 2;

#pragma unroll
        for (int k = 0; k < 8; k++) {
            uint32_t af[2][4], bf[4][4];
#pragma unroll
            for (int mi = 0; mi < 2; mi++) ldm4(af[mi], aaddr[mi] + k * 32);
#pragma unroll
            for (int nt = 0; nt < 4; nt++) ldm4(bf[nt], baddr[nt] + k * 32);
#pragma unroll
            for (int mi = 0; mi < 2; mi++)
#pragma unroll
                for (int ni = 0; ni < 8; ni++)
                    mma_f16(acc[mi][ni], af[mi],
                            bf[ni >> 1][(ni & 1) * 2], bf[ni >> 1][(ni & 1) * 2 + 1]);
        }

        // ---- epilogue: transform + store ----
        {
            const size_t rbase = (size_t)t * MT + g * GM + wm + (lane >> 2);
#pragma unroll
            for (int mi = 0; mi < 2; mi++) {
                float* p0 = outb + (rbase + mi * 16) * YD;
                float* p1 = p0 + 8 * YD;
#pragma unroll
                for (int ni = 0; ni < 8; ni++) {
                    const int c = wn + ni * 8 + 2 * (lane & 3);
                    float2 v0, v1;
                    if (branch == 0) {
                        const float2 bb = *reinterpret_cast<const float2*>(bsm + c);
                        v0.x = acc[mi][ni][0] + bb.x;  v0.y = acc[mi][ni][1] + bb.y;
                        v1.x = acc[mi][ni][2] + bb.x;  v1.y = acc[mi][ni][3] + bb.y;
                    } else {
                        v0.x = __logf(acc[mi][ni][0]);  v0.y = __logf(acc[mi][ni][1]);
                        v1.x = __logf(acc[mi][ni][2]);  v1.y = __logf(acc[mi][ni][3]);
                    }
                    *reinterpret_cast<float2*>(p0 + c) = v0;
                    *reinterpret_cast<float2*>(p1 + c) = v1;
                }
            }
        }

        // ---- drain cp.async, convert into the other A buffer (group-local) ----
        if (has_next) {
            CP_WAIT0();
            char* dst = abuf_c + (cur ^ 1) * A_BUF;
#pragma unroll
            for (int i = 0; i < 8; i++) {
                const int idx = gtid + 256 * i;
                float4 v = reinterpret_cast<const float4*>(stg_c)[idx];
                const int r = idx >> 5, c4 = idx & 31;
                cvt_store(dst, r * ROW_B + c4 * 8, v, branch);
            }
        }
        GBAR(1 + g);   // group-scope: next-buffer converted before next MMA reads it
    }
}

// ---------------- launch ----------------
extern "C" void kernel_launch(void* const* d_in, const int* in_sizes, int n_in,
                              void* d_out, int out_size) {
    const float* mean   = (const float*)d_in[0];
    const float* logvar = (const float*)d_in[1];
    const float* W      = (const float*)d_in[2];
    const float* bias   = (const float*)d_in[3];
    float* out = (float*)d_out;

    cudaFuncSetAttribute(lindec_kernel, cudaFuncAttributeMaxDynamicSharedMemorySize, SM_TOTAL);

    dim3 grid(GX, 2, 2);   // x: M-tile stride groups, y: N half, z: branch
    lindec_kernel<<<grid, NTHREADS, SM_TOTAL>>>(mean, logvar, W, bias, out);
}

// round 14
// speedup vs baseline: 1.2715x; 1.2069x over previous
#include <cuda_runtime.h>
#include <cuda_fp16.h>
#include <cstdint>

// ---------------------------------------------------------------------------
// LinearDecoder: mean_out = mean @ W^T + b ; logv = log((W*W) @ exp(logvar))
// B=131072, XDIM=128, YDIM=512. fp16 mma.sync, f32 accumulate.
// 512 threads/CTA, two 8-warp groups with private double-buffered A.
// B (W slice) resident in SMEM with row PERMUTATION so each thread's 4
// epilogue values hit 4 consecutive output columns -> STG.128.
// Output: [mean_out][logv], f32.
// ---------------------------------------------------------------------------

#define DEVINL __device__ __forceinline__

static constexpr int BATCH    = 131072;
static constexpr int XD       = 128;            // K
static constexpr int YD       = 512;            // total N
static constexpr int MT       = 128;            // M tile (two 64-row groups)
static constexpr int GM       = 64;             // rows per group
static constexpr int NT       = 256;            // N per CTA
static constexpr int M_TILES  = BATCH / MT;     // 1024
static constexpr int GX       = 37;             // 37*2*2 = 148 CTAs = 1 wave
static constexpr int NTHREADS = 512;            // 16 warps: 2 groups x (2m x 4n)

// fp16 rows padded to 136 halves (272 B): ldmatrix conflict-free.
static constexpr int ROW_H   = 136;
static constexpr int ROW_B   = ROW_H * 2;       // 272
static constexpr int SM_B    = 0;                               // half[256][136]
static constexpr int SM_BIAS = SM_B + NT * ROW_B;               // 69632 (+1024)
static constexpr int SM_A    = SM_BIAS + 1024;                  // 70656
static constexpr int A_BUF   = GM * ROW_B;                      // 17408
static constexpr int SM_ST   = SM_A + 4 * A_BUF;                // 140288
static constexpr int ST_BUF  = GM * XD * 4;                     // 32768
static constexpr int SM_TOTAL= SM_ST + 2 * ST_BUF;              // 205824 bytes

// B-row permutation: smem logical row r holds W physical row p(r).
// Thread's (2 cols from n8-tile 2k) + (2 cols from tile 2k+1) become 4
// consecutive physical columns.
DEVINL int bperm(int r) {
    return (r & ~15) | (((r >> 1) & 3) << 2) | (((r >> 3) & 1) << 1) | (r & 1);
}

// ---------------- PTX helpers ----------------
DEVINL uint32_t smem_u32(const void* p) {
    uint32_t a;
    asm("{ .reg .u64 t; cvta.to.shared.u64 t, %1; cvt.u32.u64 %0, t; }" : "=r"(a) : "l"(p));
    return a;
}
DEVINL void ldm4(uint32_t* r, uint32_t addr) {
    asm volatile("ldmatrix.sync.aligned.m8n8.x4.shared.b16 {%0,%1,%2,%3}, [%4];"
                 : "=r"(r[0]), "=r"(r[1]), "=r"(r[2]), "=r"(r[3]) : "r"(addr));
}
DEVINL void mma_f16(float* c, const uint32_t* a, uint32_t b0, uint32_t b1) {
    asm volatile("mma.sync.aligned.m16n8k16.row.col.f32.f16.f16.f32 "
                 "{%0,%1,%2,%3}, {%4,%5,%6,%7}, {%8,%9}, {%0,%1,%2,%3};"
                 : "+f"(c[0]), "+f"(c[1]), "+f"(c[2]), "+f"(c[3])
                 : "r"(a[0]), "r"(a[1]), "r"(a[2]), "r"(a[3]), "r"(b0), "r"(b1));
}
DEVINL void cp_async16(uint32_t smem_dst, const void* gmem_src) {
    asm volatile("cp.async.cg.shared.global [%0], [%1], 16;"
                 :: "r"(smem_dst), "l"(gmem_src) : "memory");
}
#define CP_COMMIT()  asm volatile("cp.async.commit_group;" ::: "memory")
#define CP_WAIT0()   asm volatile("cp.async.wait_group 0;"  ::: "memory")
#define GBAR(id)     asm volatile("bar.sync %0, %1;" :: "r"(id), "r"(256) : "memory")

DEVINL uint32_t h2u(__half2 h) { return *reinterpret_cast<uint32_t*>(&h); }

DEVINL void cvt_store(char* smem_c, int byte_off, float4 v, int branch) {
    if (branch) { v.x = __expf(v.x); v.y = __expf(v.y); v.z = __expf(v.z); v.w = __expf(v.w); }
    uint2 u;
    u.x = h2u(__floats2half2_rn(v.x, v.y));
    u.y = h2u(__floats2half2_rn(v.z, v.w));
    *reinterpret_cast<uint2*>(smem_c + byte_off) = u;
}

// ---------------- kernel ----------------
__global__ void __launch_bounds__(NTHREADS, 1)
lindec_kernel(const float* __restrict__ mean, const float* __restrict__ logvar,
              const float* __restrict__ W, const float* __restrict__ bias,
              float* __restrict__ out) {
    extern __shared__ char smem[];
    const uint32_t sb = smem_u32(smem);
    const int tid  = threadIdx.x;
    const int wid  = tid >> 5;
    const int lane = tid & 31;
    const int branch = blockIdx.z;          // 0: mean, 1: variance
    const int n0g    = blockIdx.y * NT;     // global N offset

    const int g    = wid >> 3;              // group 0/1 -> M rows [64g, 64g+64)
    const int gtid = tid & 255;
    const int gw   = wid & 7;
    const int wm   = (gw >> 2) * 32;        // warp M origin within group
    const int wn   = (gw & 3) * 64;         // warp N origin

    const float* Asrc = branch ? logvar : mean;
    float* outb = out + (size_t)branch * BATCH * YD + n0g;

    const uint32_t stg = sb + SM_ST + g * ST_BUF;
    char* stg_c        = smem + SM_ST + g * ST_BUF;
    char* abuf_c       = smem + SM_A + g * 2 * A_BUF;

    // ---- prologue: resident B = fp16(W[perm]) (squared for branch 1) ----
    {
        const float* Wp = W + (size_t)n0g * XD;
#pragma unroll 4
        for (int idx = tid; idx < NT * (XD / 4); idx += NTHREADS) {
            const int r = idx >> 5, c4 = idx & 31;
            const int pr = bperm(r);        // physical W row for smem logical row r
            float4 v = *reinterpret_cast<const float4*>(Wp + (size_t)pr * XD + c4 * 4);
            if (branch) { v.x *= v.x; v.y *= v.y; v.z *= v.z; v.w *= v.w; }
            uint2 u;
            u.x = h2u(__floats2half2_rn(v.x, v.y));
            u.y = h2u(__floats2half2_rn(v.z, v.w));
            *reinterpret_cast<uint2*>(smem + SM_B + r * ROW_B + c4 * 8) = u;
        }
        if (branch == 0)
            for (int n = tid; n < NT; n += NTHREADS)   // bias in PHYSICAL order
                reinterpret_cast<float*>(smem + SM_BIAS)[n] = bias[n0g + n];
    }

    // ---- prologue: tile 0 A half for this group ----
    {
        const float* src = Asrc + ((size_t)blockIdx.x * MT + g * GM) * XD;
#pragma unroll
        for (int i = 0; i < 8; i++) {
            const int idx = gtid + 256 * i;
            cp_async16(stg + idx * 16, src + idx * 4);
        }
        CP_COMMIT(); CP_WAIT0();
#pragma unroll
        for (int i = 0; i < 8; i++) {
            const int idx = gtid + 256 * i;
            float4 v = reinterpret_cast<const float4*>(stg_c)[idx];
            const int r = idx >> 5, c4 = idx & 31;
            cvt_store(abuf_c, r * ROW_B + c4 * 8, v, branch);
        }
    }
    __syncthreads();

    // ldmatrix per-lane addressing
    const int a_r = lane & 15;
    const int a_c = (lane >> 4) * 8;
    const int b_r = (lane & 7) + ((lane >> 4) << 3);
    const int b_c = ((lane >> 3) & 1) * 8;

    uint32_t baddr[4];
#pragma unroll
    for (int nt = 0; nt < 4; nt++)
        baddr[nt] = sb + SM_B + (wn + nt * 16 + b_r) * ROW_B + b_c * 2;

    const float* bsm = reinterpret_cast<const float*>(smem + SM_BIAS);

    int it = 0;
    for (int t = blockIdx.x; t < M_TILES; t += GX, ++it) {
        const int cur = it & 1;
        const bool has_next = (t + GX) < M_TILES;

        if (has_next) {
            const float* src = Asrc + ((size_t)(t + GX) * MT + g * GM) * XD;
#pragma unroll
            for (int i = 0; i < 8; i++) {
                const int idx = gtid + 256 * i;
                cp_async16(stg + idx * 16, src + idx * 4);
            }
            CP_COMMIT();
        }

        // ---- MMA: 32x64 per warp, K=128 in 8 k16 steps ----
        float acc[2][8][4];
#pragma unroll
        for (int mi = 0; mi < 2; mi++)
#pragma unroll
            for (int ni = 0; ni < 8; ni++)
#pragma unroll
                for (int q = 0; q < 4; q++) acc[mi][ni][q] = 0.f;

        uint32_t aaddr[2];
#pragma unroll
        for (int mi = 0; mi < 2; mi++)
            aaddr[mi] = sb + SM_A + (g * 2 + cur) * A_BUF
                      + (wm + mi * 16 + a_r) * ROW_B + a_c * 2;

#pragma unroll
        for (int k = 0; k < 8; k++) {
            uint32_t af[2][4], bf[4][4];
#pragma unroll
            for (int mi = 0; mi < 2; mi++) ldm4(af[mi], aaddr[mi] + k * 32);
#pragma unroll
            for (int nt = 0; nt < 4; nt++) ldm4(bf[nt], baddr[nt] + k * 32);
#pragma unroll
            for (int mi = 0; mi < 2; mi++)
#pragma unroll
                for (int ni = 0; ni < 8; ni++)
                    mma_f16(acc[mi][ni], af[mi],
                            bf[ni >> 1][(ni & 1) * 2], bf[ni >> 1][(ni & 1) * 2 + 1]);
        }

        // ---- epilogue: 4 consecutive physical cols per thread -> STG.128 ----
        {
            const size_t rbase = (size_t)t * MT + g * GM + wm + (lane >> 2);
#pragma unroll
            for (int mi = 0; mi < 2; mi++) {
                float* p0 = outb + (rbase + mi * 16) * YD;
                float* p1 = p0 + 8 * YD;
#pragma unroll
                for (int pr = 0; pr < 4; pr++) {
                    const int c = wn + pr * 16 + 4 * (lane & 3);
                    const int e = pr * 2, o = pr * 2 + 1;
                    float4 v0, v1;
                    v0.x = acc[mi][e][0]; v0.y = acc[mi][e][1];
                    v0.z = acc[mi][o][0]; v0.w = acc[mi][o][1];
                    v1.x = acc[mi][e][2]; v1.y = acc[mi][e][3];
                    v1.z = acc[mi][o][2]; v1.w = acc[mi][o][3];
                    if (branch == 0) {
                        const float4 bb = *reinterpret_cast<const float4*>(bsm + c);
                        v0.x += bb.x; v0.y += bb.y; v0.z += bb.z; v0.w += bb.w;
                        v1.x += bb.x; v1.y += bb.y; v1.z += bb.z; v1.w += bb.w;
                    } else {
                        v0.x = __logf(v0.x); v0.y = __logf(v0.y);
                        v0.z = __logf(v0.z); v0.w = __logf(v0.w);
                        v1.x = __logf(v1.x); v1.y = __logf(v1.y);
                        v1.z = __logf(v1.z); v1.w = __logf(v1.w);
                    }
                    *reinterpret_cast<float4*>(p0 + c) = v0;
                    *reinterpret_cast<float4*>(p1 + c) = v1;
                }
            }
        }

        // ---- drain cp.async, convert into the other A buffer ----
        if (has_next) {
            CP_WAIT0();
            char* dst = abuf_c + (cur ^ 1) * A_BUF;
#pragma unroll
            for (int i = 0; i < 8; i++) {
                const int idx = gtid + 256 * i;
                float4 v = reinterpret_cast<const float4*>(stg_c)[idx];
                const int r = idx >> 5, c4 = idx & 31;
                cvt_store(dst, r * ROW_B + c4 * 8, v, branch);
            }
        }
        GBAR(1 + g);
    }
}

// ---------------- launch ----------------
extern "C" void kernel_launch(void* const* d_in, const int* in_sizes, int n_in,
                              void* d_out, int out_size) {
    const float* mean   = (const float*)d_in[0];
    const float* logvar = (const float*)d_in[1];
    const float* W      = (const float*)d_in[2];
    const float* bias   = (const float*)d_in[3];
    float* out = (float*)d_out;

    cudaFuncSetAttribute(lindec_kernel, cudaFuncAttributeMaxDynamicSharedMemorySize, SM_TOTAL);

    dim3 grid(GX, 2, 2);   // x: M-tile stride groups, y: N half, z: branch
    lindec_kernel<<<grid, NTHREADS, SM_TOTAL>>>(mean, logvar, W, bias, out);
}